// round 2
// baseline (speedup 1.0000x reference)
#include <cuda_runtime.h>

// LIF: v = alpha*v + beta*c ; s = (v >= 1) ; v reset to 0 where spiked.
// T=2048 sequential steps, N=32768 independent neurons.
//
// Speculative design: spikes are ~6.3-sigma events (P ~ 1e-10), so the main
// kernel runs the pure linear recurrence (no reset), writes spikes as zeros,
// and tracks a per-neuron running max. A fixup kernel re-runs (with exact
// unfused reference arithmetic and reset) any neuron whose max crossed
// threshold, overwriting its output columns. Exact for arbitrary inputs.
//
// Main kernel: 2 neurons/thread packed in f32x2 (Blackwell packed fp32 via
// inline PTX), 512 warps, 16-deep ping-pong prefetch of currents.

#define LIF_T 2048
#define LIF_N 32768
#define LIF_S (LIF_N / 2)      // row stride in 8-byte (float2) units
#define LIF_U 16               // prefetch batch depth
#define LIF_BLK 64             // threads per block (2 warps) -> 256 blocks

__device__ float g_vmax[LIF_N];

__device__ __forceinline__ void lif_load_batch(const unsigned long long* cp,
                                               unsigned long long (&b)[LIF_U]) {
#pragma unroll
    for (int i = 0; i < LIF_U; i++) b[i] = __ldcs(cp + i * LIF_S);
}

__device__ __forceinline__ void lif_compute_batch(const unsigned long long (&b)[LIF_U],
                                                  unsigned long long& v,
                                                  unsigned long long a2,
                                                  unsigned long long b2,
                                                  unsigned long long z,
                                                  float& m0, float& m1,
                                                  unsigned long long* sp,
                                                  unsigned long long* vp) {
#pragma unroll
    for (int i = 0; i < LIF_U; i++) {
        unsigned long long bc, vn;
        // bc = beta * c   (off the sequential dependency chain)
        asm("mul.rn.f32x2 %0, %1, %2;" : "=l"(bc) : "l"(b2), "l"(b[i]));
        // v = alpha * v + bc   (the recurrence chain: one packed FFMA)
        asm("fma.rn.f32x2 %0, %1, %2, %3;" : "=l"(vn) : "l"(a2), "l"(v), "l"(bc));
        v = vn;
        float lo, hi;
        asm("mov.b64 {%0,%1}, %2;" : "=f"(lo), "=f"(hi) : "l"(v));
        m0 = fmaxf(m0, lo);
        m1 = fmaxf(m1, hi);
        __stcs(sp + i * LIF_S, z);   // speculative spike = 0
        __stcs(vp + i * LIF_S, v);   // no-reset voltage
    }
}

__global__ __launch_bounds__(LIF_BLK)
void lif_main(const float* __restrict__ currents,
              const float* __restrict__ v0,
              float* __restrict__ out)
{
    const int tid = blockIdx.x * LIF_BLK + threadIdx.x;   // 0..16383
    const int n = tid * 2;

    const float alpha = 0.95122942450071400909f;  // f32(exp(-1/20))
    const float beta  = 0.04877057549928599090f;  // f32(1 - exp(-1/20))

    unsigned long long a2, b2, v;
    asm("mov.b64 %0, {%1,%1};" : "=l"(a2) : "f"(alpha));
    asm("mov.b64 %0, {%1,%1};" : "=l"(b2) : "f"(beta));
    {
        float v0lo = v0[n], v0hi = v0[n + 1];
        asm("mov.b64 %0, {%1,%2};" : "=l"(v) : "f"(v0lo), "f"(v0hi));
    }
    const unsigned long long z = 0ull;
    float m0 = -3.0e38f, m1 = -3.0e38f;

    const unsigned long long* cp = (const unsigned long long*)currents + tid;
    unsigned long long* sp = (unsigned long long*)out + tid;                          // spikes
    unsigned long long* vp = (unsigned long long*)out + (size_t)LIF_T * LIF_S + tid;  // voltages

    unsigned long long bufA[LIF_U], bufB[LIF_U];

    lif_load_batch(cp, bufA);
    cp += LIF_U * LIF_S;

    for (int t0 = 0; t0 < LIF_T; t0 += 2 * LIF_U) {
        // load batch t0+U while computing batch t0
        lif_load_batch(cp, bufB);
        cp += LIF_U * LIF_S;
        lif_compute_batch(bufA, v, a2, b2, z, m0, m1, sp, vp);
        sp += LIF_U * LIF_S;
        vp += LIF_U * LIF_S;

        // load batch t0+2U (if any) while computing batch t0+U
        if (t0 + 2 * LIF_U < LIF_T) {
            lif_load_batch(cp, bufA);
            cp += LIF_U * LIF_S;
        }
        lif_compute_batch(bufB, v, a2, b2, z, m0, m1, sp, vp);
        sp += LIF_U * LIF_S;
        vp += LIF_U * LIF_S;
    }

    ((float2*)g_vmax)[tid] = make_float2(m0, m1);
}

// Fixup: exact sequential reference recurrence (unfused mul/add, with reset)
// for any neuron whose speculative max crossed threshold. Almost never runs.
__global__ void lif_fixup(const float* __restrict__ currents,
                          const float* __restrict__ v0,
                          float* __restrict__ out)
{
    const int n = blockIdx.x * blockDim.x + threadIdx.x;
    if (n >= LIF_N) return;
    if (g_vmax[n] < 1.0f) return;

    const float alpha = 0.95122942450071400909f;
    const float beta  = 0.04877057549928599090f;

    float v = v0[n];
    float* sp = out + n;
    float* vp = out + (size_t)LIF_T * LIF_N + n;

    for (int t = 0; t < LIF_T; t++) {
        const float c = currents[(size_t)t * LIF_N + n];
        v = __fadd_rn(__fmul_rn(alpha, v), __fmul_rn(beta, c));
        const float s = (v >= 1.0f) ? 1.0f : 0.0f;
        if (s == 1.0f) v = 0.0f;     // v*(1-s) + 0*s with s=1 -> exactly 0
        sp[(size_t)t * LIF_N] = s;
        vp[(size_t)t * LIF_N] = v;
    }
}

extern "C" void kernel_launch(void* const* d_in, const int* in_sizes, int n_in,
                              void* d_out, int out_size)
{
    const float* currents = (const float*)d_in[0];   // (T, N) fp32
    const float* v0       = (const float*)d_in[1];   // (N,)  fp32
    float* out            = (float*)d_out;           // (2, T, N): spikes, voltages

    (void)in_sizes; (void)n_in; (void)out_size;

    lif_main<<<LIF_S / LIF_BLK, LIF_BLK>>>(currents, v0, out);     // 256 blocks x 64
    lif_fixup<<<LIF_N / 256, 256>>>(currents, v0, out);            // cheap guard pass
}

// round 3
// speedup vs baseline: 1.1622x; 1.1622x over previous
#include <cuda_runtime.h>

// LIF: v = alpha*v + beta*c ; s = (v >= 1) ; v reset to 0 where spiked.
// T=2048 sequential steps, N=32768 independent neurons.
//
// Speculative no-reset main kernel (spikes are ~6.3-sigma events): pure linear
// recurrence in packed f32x2 (2 neurons/thread), spikes written as zeros,
// per-neuron running max tracked. Fixup kernel re-runs exact reference
// arithmetic (with reset) for any neuron whose max neared threshold.
//
// R3 change: 4-deep rotating prefetch (~48 LDG.64 in flight per thread,
// ~6.3 MB chip-wide) to lift the read stream off the latency wall
// (Little's law: 2 MB in flight @ ~1.1us loaded latency capped reads at
// ~1.8 TB/s, which matched the measured 154us exactly).

#define LIF_T   2048
#define LIF_N   32768
#define LIF_S   (LIF_N / 2)     // row stride in float2 units
#define LIF_U   16              // steps per batch
#define LIF_NB  (LIF_T / LIF_U) // 128 batches
#define LIF_BLK 64

__device__ float g_vmax[LIF_N];

__device__ __forceinline__ void lif_load(const unsigned long long*& cp, int& nl,
                                         unsigned long long (&b)[LIF_U]) {
    if (nl < LIF_NB) {
#pragma unroll
        for (int i = 0; i < LIF_U; i++) b[i] = __ldcs(cp + i * LIF_S);
        cp += LIF_U * LIF_S;
    }
    nl++;
}

__device__ __forceinline__ void lif_compute(const unsigned long long (&b)[LIF_U],
                                            unsigned long long& v,
                                            unsigned long long a2,
                                            unsigned long long b2,
                                            float& m0, float& m1,
                                            unsigned long long*& sp,
                                            unsigned long long*& vp) {
#pragma unroll
    for (int i = 0; i < LIF_U; i++) {
        unsigned long long bc, vn;
        // bc = beta * c  (off the sequential dependency chain)
        asm("mul.rn.f32x2 %0, %1, %2;" : "=l"(bc) : "l"(b2), "l"(b[i]));
        // v = alpha * v + bc  (recurrence chain: one packed FFMA, lat 4)
        asm("fma.rn.f32x2 %0, %1, %2, %3;" : "=l"(vn) : "l"(a2), "l"(v), "l"(bc));
        v = vn;
        float lo, hi;
        asm("mov.b64 {%0,%1}, %2;" : "=f"(lo), "=f"(hi) : "l"(v));
        m0 = fmaxf(m0, lo);
        m1 = fmaxf(m1, hi);
        __stcs(sp + i * LIF_S, 0ull);   // speculative spike = 0
        __stcs(vp + i * LIF_S, v);      // no-reset voltage
    }
    sp += LIF_U * LIF_S;
    vp += LIF_U * LIF_S;
}

__global__ __launch_bounds__(LIF_BLK)
void lif_main(const float* __restrict__ currents,
              const float* __restrict__ v0,
              float* __restrict__ out)
{
    const int tid = blockIdx.x * LIF_BLK + threadIdx.x;   // 0..16383
    const int n = tid * 2;

    const float alpha = 0.95122942450071400909f;  // f32(exp(-1/20))
    const float beta  = 0.04877057549928599090f;  // f32(1 - exp(-1/20))

    unsigned long long a2, b2, v;
    asm("mov.b64 %0, {%1,%1};" : "=l"(a2) : "f"(alpha));
    asm("mov.b64 %0, {%1,%1};" : "=l"(b2) : "f"(beta));
    {
        float v0lo = v0[n], v0hi = v0[n + 1];
        asm("mov.b64 %0, {%1,%2};" : "=l"(v) : "f"(v0lo), "f"(v0hi));
    }
    float m0 = -3.0e38f, m1 = -3.0e38f;

    const unsigned long long* cp = (const unsigned long long*)currents + tid;
    unsigned long long* sp = (unsigned long long*)out + tid;                          // spikes
    unsigned long long* vp = (unsigned long long*)out + (size_t)LIF_T * LIF_S + tid;  // voltages

    unsigned long long bA[LIF_U], bB[LIF_U], bC[LIF_U], bD[LIF_U];
    int nl = 0;   // next batch index to load

    // Prime 3 batches ahead (48 loads in flight).
    lif_load(cp, nl, bA);
    lif_load(cp, nl, bB);
    lif_load(cp, nl, bC);

    // 128 batches, unrolled by 4 slots: load stays 3 batches ahead of compute.
#pragma unroll 1
    for (int it = 0; it < LIF_NB / 4; it++) {
        lif_load(cp, nl, bD);
        lif_compute(bA, v, a2, b2, m0, m1, sp, vp);
        lif_load(cp, nl, bA);
        lif_compute(bB, v, a2, b2, m0, m1, sp, vp);
        lif_load(cp, nl, bB);
        lif_compute(bC, v, a2, b2, m0, m1, sp, vp);
        lif_load(cp, nl, bC);
        lif_compute(bD, v, a2, b2, m0, m1, sp, vp);
    }

    ((float2*)g_vmax)[tid] = make_float2(m0, m1);
}

// Fixup: exact sequential reference recurrence (unfused mul/add, with reset)
// for any neuron whose speculative max neared threshold. Almost never runs.
__global__ void lif_fixup(const float* __restrict__ currents,
                          const float* __restrict__ v0,
                          float* __restrict__ out)
{
    const int n = blockIdx.x * blockDim.x + threadIdx.x;
    if (n >= LIF_N) return;
    if (g_vmax[n] < 0.999f) return;   // margin absorbs fused-vs-unfused drift

    const float alpha = 0.95122942450071400909f;
    const float beta  = 0.04877057549928599090f;

    float v = v0[n];
    float* sp = out + n;
    float* vp = out + (size_t)LIF_T * LIF_N + n;

    for (int t = 0; t < LIF_T; t++) {
        const float c = currents[(size_t)t * LIF_N + n];
        v = __fadd_rn(__fmul_rn(alpha, v), __fmul_rn(beta, c));
        const float s = (v >= 1.0f) ? 1.0f : 0.0f;
        if (s == 1.0f) v = 0.0f;     // exact reset
        sp[(size_t)t * LIF_N] = s;
        vp[(size_t)t * LIF_N] = v;
    }
}

extern "C" void kernel_launch(void* const* d_in, const int* in_sizes, int n_in,
                              void* d_out, int out_size)
{
    const float* currents = (const float*)d_in[0];   // (T, N) fp32
    const float* v0       = (const float*)d_in[1];   // (N,)  fp32
    float* out            = (float*)d_out;           // (2, T, N): spikes, voltages

    (void)in_sizes; (void)n_in; (void)out_size;

    lif_main<<<LIF_S / LIF_BLK, LIF_BLK>>>(currents, v0, out);   // 256 blocks x 64
    lif_fixup<<<LIF_N / 256, 256>>>(currents, v0, out);          // cheap guard pass
}

// round 8
// speedup vs baseline: 1.1770x; 1.0127x over previous
#include <cuda_runtime.h>

// LIF: v = alpha*v + beta*c ; s = (v >= 1) ; v reset to 0 where spiked.
// T=2048 sequential steps, N=32768 independent neurons.
//
// Speculative no-reset kernel (spikes are ~6.3-sigma events, P~1e-10): pure
// linear recurrence in packed f32x2 (2 neurons/thread), spikes written as
// zeros, per-neuron running max tracked in registers. 4-slot rotating
// prefetch keeps ~48 LDG.64 in flight per thread (~6.3 MB chip-wide),
// saturating DRAM (measured 6.3 TB/s effective at R3).
//
// R4-R7 (resubmit, unmeasured due to broker timeouts): fixup folded into the
// kernel tail — a thread whose running max neared threshold re-runs the
// exact scalar reference recurrence (with reset) for that neuron and
// overwrites its columns. Removes the second kernel launch (~6-7us of
// launch latency + idle-gap).

#define LIF_T   2048
#define LIF_N   32768
#define LIF_S   (LIF_N / 2)     // row stride in float2 units
#define LIF_U   16              // steps per batch
#define LIF_NB  (LIF_T / LIF_U) // 128 batches
#define LIF_BLK 64

__device__ __forceinline__ void lif_load(const unsigned long long*& cp, int& nl,
                                         unsigned long long (&b)[LIF_U]) {
    if (nl < LIF_NB) {
#pragma unroll
        for (int i = 0; i < LIF_U; i++) b[i] = __ldcs(cp + i * LIF_S);
        cp += LIF_U * LIF_S;
    }
    nl++;
}

__device__ __forceinline__ void lif_compute(const unsigned long long (&b)[LIF_U],
                                            unsigned long long& v,
                                            unsigned long long a2,
                                            unsigned long long b2,
                                            float& m0, float& m1,
                                            unsigned long long*& sp,
                                            unsigned long long*& vp) {
#pragma unroll
    for (int i = 0; i < LIF_U; i++) {
        unsigned long long bc, vn;
        // bc = beta * c  (off the sequential dependency chain)
        asm("mul.rn.f32x2 %0, %1, %2;" : "=l"(bc) : "l"(b2), "l"(b[i]));
        // v = alpha * v + bc  (recurrence chain: one packed FFMA, lat 4)
        asm("fma.rn.f32x2 %0, %1, %2, %3;" : "=l"(vn) : "l"(a2), "l"(v), "l"(bc));
        v = vn;
        float lo, hi;
        asm("mov.b64 {%0,%1}, %2;" : "=f"(lo), "=f"(hi) : "l"(v));
        m0 = fmaxf(m0, lo);
        m1 = fmaxf(m1, hi);
        __stcs(sp + i * LIF_S, 0ull);   // speculative spike = 0
        __stcs(vp + i * LIF_S, v);      // no-reset voltage
    }
    sp += LIF_U * LIF_S;
    vp += LIF_U * LIF_S;
}

__global__ __launch_bounds__(LIF_BLK)
void lif_main(const float* __restrict__ currents,
              const float* __restrict__ v0,
              float* __restrict__ out)
{
    const int tid = blockIdx.x * LIF_BLK + threadIdx.x;   // 0..16383

    const float alpha = 0.95122942450071400909f;  // f32(exp(-1/20))
    const float beta  = 0.04877057549928599090f;  // f32(1 - exp(-1/20))

    unsigned long long a2, b2, v;
    asm("mov.b64 %0, {%1,%1};" : "=l"(a2) : "f"(alpha));
    asm("mov.b64 %0, {%1,%1};" : "=l"(b2) : "f"(beta));
    {
        float v0lo = v0[2 * tid], v0hi = v0[2 * tid + 1];
        asm("mov.b64 %0, {%1,%2};" : "=l"(v) : "f"(v0lo), "f"(v0hi));
    }
    float m0 = -3.0e38f, m1 = -3.0e38f;

    const unsigned long long* cp = (const unsigned long long*)currents + tid;
    unsigned long long* sp = (unsigned long long*)out + tid;                          // spikes
    unsigned long long* vp = (unsigned long long*)out + (size_t)LIF_T * LIF_S + tid;  // voltages

    unsigned long long bA[LIF_U], bB[LIF_U], bC[LIF_U], bD[LIF_U];
    int nl = 0;   // next batch index to load

    // Prime 3 batches ahead (48 loads in flight).
    lif_load(cp, nl, bA);
    lif_load(cp, nl, bB);
    lif_load(cp, nl, bC);

    // 128 batches, 4 rotating slots: loads stay 3 batches ahead of compute.
#pragma unroll 1
    for (int it = 0; it < LIF_NB / 4; it++) {
        lif_load(cp, nl, bD);
        lif_compute(bA, v, a2, b2, m0, m1, sp, vp);
        lif_load(cp, nl, bA);
        lif_compute(bB, v, a2, b2, m0, m1, sp, vp);
        lif_load(cp, nl, bB);
        lif_compute(bC, v, a2, b2, m0, m1, sp, vp);
        lif_load(cp, nl, bC);
        lif_compute(bD, v, a2, b2, m0, m1, sp, vp);
    }

    // ---- In-thread fixup (statistically never taken; exact if it is) ----
    // If a speculative max neared threshold, re-run the exact reference
    // recurrence (unfused mul/add, with reset) for that neuron and
    // overwrite its output columns. 0.999 margin absorbs fused-vs-unfused
    // drift between the speculative and exact trajectories.
    if (m0 >= 0.999f || m1 >= 0.999f) {
#pragma unroll 1
        for (int k = 0; k < 2; k++) {
            const float mk = (k == 0) ? m0 : m1;
            if (mk < 0.999f) continue;
            const int n = 2 * tid + k;
            float vs = v0[n];
            float* sfp = out + n;
            float* vfp = out + (size_t)LIF_T * LIF_N + n;
#pragma unroll 1
            for (int t = 0; t < LIF_T; t++) {
                const float c = __ldg(currents + (size_t)t * LIF_N + n);
                vs = __fadd_rn(__fmul_rn(alpha, vs), __fmul_rn(beta, c));
                const float s = (vs >= 1.0f) ? 1.0f : 0.0f;
                if (s == 1.0f) vs = 0.0f;          // exact reset
                sfp[(size_t)t * LIF_N] = s;
                vfp[(size_t)t * LIF_N] = vs;
            }
        }
    }
}

extern "C" void kernel_launch(void* const* d_in, const int* in_sizes, int n_in,
                              void* d_out, int out_size)
{
    const float* currents = (const float*)d_in[0];   // (T, N) fp32
    const float* v0       = (const float*)d_in[1];   // (N,)  fp32
    float* out            = (float*)d_out;           // (2, T, N): spikes, voltages

    (void)in_sizes; (void)n_in; (void)out_size;

    lif_main<<<LIF_S / LIF_BLK, LIF_BLK>>>(currents, v0, out);   // 256 blocks x 64
}